// round 8
// baseline (speedup 1.0000x reference)
#include <cuda_runtime.h>
#include <cstdint>

// ---------------------------------------------------------------------------
// Round 7: issue-slot diet on the R6 structure.
//   - no tf32 cvt in hot loop (HW truncates fp32 -> tf32 in mma.sync)
//   - relu + sumsq in staging phase (per-thread accumulators; warp w owns
//     points {w, w+8} exclusively -> no atomics, no duplication)
//   - mma inner loop: ldmatrix + B LDG.128 + mma only
// ---------------------------------------------------------------------------

#define MPTS   16
#define TPB    256
#define KC     128
#define KPAD   12288
#define NCH    (KPAD / KC)
#define SA     132            // A smem row stride (u32)
#define RS     72             // reduce buffer row stride (floats)
#define NK8    (KPAD / 8)     // 1536
#define NB     172            // base-table entries per point

__device__ uint4 g_Wf4[NK8 * 4 * 32];  // [(K8*4 + nt2)*32 + lane] = {b0e,b1e,b0o,b1o}

__constant__ int c_OFF7[7][3] = {
    {0,0,0},{1,0,0},{-1,0,0},{0,1,0},{0,-1,0},{0,0,1},{0,0,-1}};
__constant__ int c_S14[14][3] = {
    {1,0,0},{-1,0,0},{0,1,0},{0,-1,0},{0,0,1},{0,0,-1},
    {1,1,1},{-1,-1,-1},{1,-1,-1},{-1,1,1},{1,1,-1},{-1,-1,1},{1,-1,1},{-1,1,-1}};
__constant__ int c_CORNER[8][3] = {
    {1,1,1},{-1,-1,-1},{1,-1,-1},{-1,1,1},{1,1,-1},{-1,-1,1},{1,-1,1},{-1,1,-1}};
__constant__ int c_ETEMP[11] = {-64,-8,-4,-2,-1,0,1,2,4,8,64};

__device__ __forceinline__ uint32_t f2tf32(float x) {
    uint32_t u;
    asm("cvt.rna.tf32.f32 %0, %1;" : "=r"(u) : "f"(x));
    return u;
}

__device__ __forceinline__ uint32_t s2u(const void* p) {
    uint32_t a;
    asm("{ .reg .u64 t; cvta.to.shared.u64 t, %1; cvt.u32.u64 %0, t; }"
        : "=r"(a) : "l"(p));
    return a;
}

__device__ __forceinline__ void mma8(float* c,
                                     uint32_t a0, uint32_t a1, uint32_t a2, uint32_t a3,
                                     uint32_t b0, uint32_t b1) {
    asm("mma.sync.aligned.m16n8k8.row.col.f32.tf32.tf32.f32 "
        "{%0,%1,%2,%3}, {%4,%5,%6,%7}, {%8,%9}, {%0,%1,%2,%3};"
        : "+f"(c[0]), "+f"(c[1]), "+f"(c[2]), "+f"(c[3])
        : "r"(a0), "r"(a1), "r"(a2), "r"(a3), "r"(b0), "r"(b1));
}

// ---------------------------------------------------------------------------
__global__ void __launch_bounds__(256)
wf_precompute_kernel(const float* __restrict__ w_down,
                     const float* __restrict__ rms_scale)
{
    int T = blockIdx.x * 256 + threadIdx.x;
    if (T >= NK8 * 4 * 32) return;
    int lane = T & 31;
    int nt2  = (T >> 5) & 3;
    int K8   = T >> 7;
    int ne = nt2 * 16 + (lane >> 2);
    int no = ne + 8;
    int k0 = K8 * 8 + (lane & 3);
    int k1 = k0 + 4;
    uint4 u;
    u.x = (k0 < 12240) ? f2tf32(w_down[k0 * 64 + ne] * rms_scale[k0]) : 0u;
    u.y = (k1 < 12240) ? f2tf32(w_down[k1 * 64 + ne] * rms_scale[k1]) : 0u;
    u.z = (k0 < 12240) ? f2tf32(w_down[k0 * 64 + no] * rms_scale[k0]) : 0u;
    u.w = (k1 < 12240) ? f2tf32(w_down[k1 * 64 + no] * rms_scale[k1]) : 0u;
    g_Wf4[T] = u;
}

// ---------------------------------------------------------------------------
// Gather 4 consecutive features via precomputed per-point base table.
__device__ __forceinline__ float4 gather4b(
    int k, const int* __restrict__ bp,
    const float* __restrict__ T0, const float* __restrict__ T1,
    const float* __restrict__ T2, const float* __restrict__ T3,
    const float* __restrict__ S1t, const float* __restrict__ S2t,
    const float* __restrict__ TF)
{
    if (k < 9520) {
        const float* tab; int r, flog, bi;
        if (k < 112)       { tab = T0; r = k;        flog = 4;  bi = 0;  }
        else if (k < 560)  { tab = T1; r = k - 112;  flog = 6;  bi = 7;  }
        else if (k < 2352) { tab = T2; r = k - 560;  flog = 8;  bi = 14; }
        else               { tab = T3; r = k - 2352; flog = 10; bi = 21; }
        int o = r >> flog;
        int f = r & ((1 << flog) - 1);
        return *reinterpret_cast<const float4*>(tab + bp[bi + o] + f);
    }
    if (k < 11312) {
        int r = k - 9520;
        return *reinterpret_cast<const float4*>(S1t + bp[28 + (r >> 6)] + (r & 63));
    }
    if (k < 11536) {
        int r = k - 11312;
        return *reinterpret_cast<const float4*>(S2t + bp[56 + (r >> 3)] + (r & 7));
    }
    if (k < 12240) {
        int r = k - 11536;
        return *reinterpret_cast<const float4*>(TF + bp[84 + (r >> 3)] + (r & 7));
    }
    return make_float4(0.f, 0.f, 0.f, 0.f);
}

// ---------------------------------------------------------------------------
__global__ void __launch_bounds__(TPB, 3)
stlt_fused_kernel(
    const float* __restrict__ d_pos, const float* __restrict__ d_dir,
    const float* __restrict__ d_t,
    const float* __restrict__ T0, const float* __restrict__ T1,
    const float* __restrict__ T2, const float* __restrict__ T3,
    const float* __restrict__ S1t, const float* __restrict__ S2t,
    const float* __restrict__ TF,
    const float* __restrict__ w_final, const float* __restrict__ b_final,
    float* __restrict__ d_out)
{
    __shared__ alignas(16) uint32_t As[2 * MPTS * SA];   // double-buffered A
    __shared__ alignas(16) float    Rbuf[MPTS * RS];
    __shared__ int      bases[MPTS * NB];
    __shared__ int      pidx[MPTS][14];
    __shared__ float    sumsq_s[MPTS];

    const int tid  = threadIdx.x;
    const int lane = tid & 31;
    const int warp = tid >> 5;
    const int kq   = warp >> 1;     // k-quarter 0..3
    const int nh   = warp & 1;      // n-half 0..1 (cols [nh*32, +32))
    const int p0   = blockIdx.x * MPTS;

    if (tid < MPTS) {
        int gp = p0 + tid;
        float px = d_pos[gp * 3 + 0];
        float py = d_pos[gp * 3 + 1];
        float pz = d_pos[gp * 3 + 2];
        pidx[tid][0]  = (int)(px * 127.0f);
        pidx[tid][1]  = (int)(py * 127.0f);
        pidx[tid][2]  = (int)(pz * 127.0f);
        pidx[tid][3]  = (int)(px * 63.0f);
        pidx[tid][4]  = (int)(py * 63.0f);
        pidx[tid][5]  = (int)(pz * 63.0f);
        pidx[tid][6]  = (int)(px * 31.0f);
        pidx[tid][7]  = (int)(py * 31.0f);
        pidx[tid][8]  = (int)(pz * 31.0f);
        pidx[tid][9]  = (int)(px * 15.0f);
        pidx[tid][10] = (int)(py * 15.0f);
        pidx[tid][11] = (int)(pz * 15.0f);
        float tv = d_t[gp];
        pidx[tid][12] = (int)(tv * 15.0f);
        pidx[tid][13] = (int)(tv * 63.0f);
    }
    __syncthreads();

    // ---- fill per-point base-address table (element offsets) --------------
    for (int e = tid; e < MPTS * NB; e += TPB) {
        int p = e / NB;
        int j = e - p * NB;
        int b;
        if (j < 28) {                       // spatial: tau = j/7, o = j%7
            int tau  = j / 7;
            int o    = j - tau * 7;
            int dlog = 7 - tau;
            int flog = 4 + 2 * tau;
            int d = 1 << dlog, m = d - 1;
            int cx = (pidx[p][tau * 3 + 0] + c_OFF7[o][0] + d) & m;
            int cy = (pidx[p][tau * 3 + 1] + c_OFF7[o][1] + d) & m;
            int cz = (pidx[p][tau * 3 + 2] + c_OFF7[o][2] + d) & m;
            b = ((((cx << dlog) | cy) << dlog) | cz) << flog;
        } else if (j < 56) {                // st1 (16,16,16,64) F=64
            int jj = j - 28;
            int si = jj >> 1;
            int tt = (jj & 1) ? -1 : 1;
            int tb = pidx[p][12], tv = pidx[p][13];
            int a  = (tb + c_S14[si][0] + 16) & 15;
            int bb = (tb + c_S14[si][1] + 16) & 15;
            int c  = (tb + c_S14[si][2] + 16) & 15;
            int dd = (tv + tt + 64) & 63;
            b = ((((((a << 4) | bb) << 4) | c) << 6) | dd) << 6;
        } else if (j < 84) {                // st2 (64,64,64,64) F=8
            int jj = j - 56;
            int si = jj >> 1;
            int tt = (jj & 1) ? -1 : 1;
            int tb = pidx[p][12], tv = pidx[p][13];
            int a  = (tb + c_S14[si][0] + 64) & 63;
            int bb = (tb + c_S14[si][1] + 64) & 63;
            int c  = (tb + c_S14[si][2] + 64) & 63;
            int dd = (tv + tt + 64) & 63;
            b = ((((((a << 6) | bb) << 6) | c) << 6) | dd) << 3;
        } else {                            // tf3 (4,4,4,65536) F=8
            int jj = j - 84;
            int ci = jj / 11;
            int ti = jj - ci * 11;
            int tb = pidx[p][12], tv = pidx[p][13];
            int a  = (tb + c_CORNER[ci][0] + 4) & 3;
            int bb = (tb + c_CORNER[ci][1] + 4) & 3;
            int c  = (tb + c_CORNER[ci][2] + 4) & 3;
            int dd = (tv + c_ETEMP[ti] + 65536) & 65535;
            b = ((((((a << 2) | bb) << 2) | c) << 16) | dd) << 3;
        }
        bases[e] = b;
    }
    __syncthreads();

    float acc[4][4];
#pragma unroll
    for (int i = 0; i < 4; i++)
#pragma unroll
        for (int j = 0; j < 4; j++) acc[i][j] = 0.f;
    // per-thread sumsq: this thread only ever touches points {warp, warp+8}
    float ss0 = 0.f, ss1 = 0.f;

    const int lm_row = ((lane >> 3) & 1) * 8 + (lane & 7);
    const int lm_kof = (lane >> 4) * 4;

    // ---- prologue: gather chunk 0 into regs (2 float4 per thread) ---------
    float4 v[2];
#pragma unroll
    for (int j = 0; j < 2; j++) {
        int i  = tid + j * TPB;
        int p  = i >> 5;
        int k4 = (i & 31) << 2;
        v[j] = gather4b(k4, bases + p * NB, T0, T1, T2, T3, S1t, S2t, TF);
    }

    for (int ch = 0; ch < NCH; ch++) {
        uint32_t* buf = As + (ch & 1) * (MPTS * SA);
        const int kb  = ch * KC;

        // ---- STS: relu + per-thread sumsq + store raw fp32 bits ----------
        {
            float4 w0 = v[0];
            w0.x = fmaxf(w0.x, 0.f); w0.y = fmaxf(w0.y, 0.f);
            w0.z = fmaxf(w0.z, 0.f); w0.w = fmaxf(w0.w, 0.f);
            ss0 += w0.x * w0.x + w0.y * w0.y + w0.z * w0.z + w0.w * w0.w;
            float4 w1 = v[1];
            w1.x = fmaxf(w1.x, 0.f); w1.y = fmaxf(w1.y, 0.f);
            w1.z = fmaxf(w1.z, 0.f); w1.w = fmaxf(w1.w, 0.f);
            ss1 += w1.x * w1.x + w1.y * w1.y + w1.z * w1.z + w1.w * w1.w;
            int i0 = tid;
            int i1 = tid + TPB;
            *reinterpret_cast<float4*>(&buf[(i0 >> 5) * SA + ((i0 & 31) << 2)]) = w0;
            *reinterpret_cast<float4*>(&buf[(i1 >> 5) * SA + ((i1 & 31) << 2)]) = w1;
        }
        __syncthreads();

        // ---- prefetch next chunk (overlaps mma) ---------------------------
        if (ch + 1 < NCH) {
#pragma unroll
            for (int j = 0; j < 2; j++) {
                int i  = tid + j * TPB;
                int p  = i >> 5;
                int k4 = (i & 31) << 2;
                v[j] = gather4b(kb + KC + k4, bases + p * NB, T0, T1, T2, T3, S1t, S2t, TF);
            }
        }

        // ---- mma: warp covers k8 in [kq*4, +4), n [nh*32, +32) ------------
        // fp32 bits fed directly to tf32 mma (HW truncates low mantissa).
#pragma unroll
        for (int g = 0; g < 4; g++) {
            int K8l = kq * 4 + g;
            int kk  = K8l * 8;
            uint32_t a0, a1, a2, a3;
            uint32_t addr = s2u(&buf[lm_row * SA + kk + lm_kof]);
            asm volatile("ldmatrix.sync.aligned.m8n8.x4.shared.b16 {%0,%1,%2,%3}, [%4];"
                         : "=r"(a0), "=r"(a1), "=r"(a2), "=r"(a3) : "r"(addr));
            const uint4* Wk = g_Wf4 + ((size_t)(ch * 16 + K8l) << 7) + lane;
#pragma unroll
            for (int q = 0; q < 2; q++) {
                uint4 bq = Wk[(2 * nh + q) * 32];
                mma8(acc[2 * q],     a0, a1, a2, a3, bq.x, bq.y);
                mma8(acc[2 * q + 1], a0, a1, a2, a3, bq.z, bq.w);
            }
        }
    }

    // ---- sumsq: warp-wide reduce, single writer per point -----------------
#pragma unroll
    for (int s = 16; s >= 1; s >>= 1) {
        ss0 += __shfl_xor_sync(0xffffffffu, ss0, s);
        ss1 += __shfl_xor_sync(0xffffffffu, ss1, s);
    }
    if (lane == 0) {
        sumsq_s[warp]     = ss0;   // point index = warp   (i0>>5 == warp)
        sumsq_s[warp + 8] = ss1;   // point index = warp+8 (i1>>5 == warp+8)
    }

    // ---- cross-k acc reduction (serialized by kq; both nh in parallel) ----
    {
        int row = lane >> 2;
        int cb  = nh * 32 + (lane & 3) * 2;
        if (kq == 3) {
#pragma unroll
            for (int nt = 0; nt < 4; nt++) {
                int col = cb + nt * 8;
                Rbuf[row * RS + col]           = acc[nt][0];
                Rbuf[row * RS + col + 1]       = acc[nt][1];
                Rbuf[(row + 8) * RS + col]     = acc[nt][2];
                Rbuf[(row + 8) * RS + col + 1] = acc[nt][3];
            }
        }
        __syncthreads();
        if (kq == 2) {
#pragma unroll
            for (int nt = 0; nt < 4; nt++) {
                int col = cb + nt * 8;
                Rbuf[row * RS + col]           += acc[nt][0];
                Rbuf[row * RS + col + 1]       += acc[nt][1];
                Rbuf[(row + 8) * RS + col]     += acc[nt][2];
                Rbuf[(row + 8) * RS + col + 1] += acc[nt][3];
            }
        }
        __syncthreads();
        if (kq == 1) {
#pragma unroll
            for (int nt = 0; nt < 4; nt++) {
                int col = cb + nt * 8;
                Rbuf[row * RS + col]           += acc[nt][0];
                Rbuf[row * RS + col + 1]       += acc[nt][1];
                Rbuf[(row + 8) * RS + col]     += acc[nt][2];
                Rbuf[(row + 8) * RS + col + 1] += acc[nt][3];
            }
        }
        __syncthreads();
        if (kq == 0) {
            float inv0 = 1.0f / (sqrtf(sumsq_s[row] * (1.0f / 12240.0f)) + 1e-8f);
            float inv1 = 1.0f / (sqrtf(sumsq_s[row + 8] * (1.0f / 12240.0f)) + 1e-8f);
#pragma unroll
            for (int nt = 0; nt < 4; nt++) {
                int col = cb + nt * 8;
                Rbuf[row * RS + col]           = fmaxf((acc[nt][0] + Rbuf[row * RS + col]) * inv0, 0.f);
                Rbuf[row * RS + col + 1]       = fmaxf((acc[nt][1] + Rbuf[row * RS + col + 1]) * inv0, 0.f);
                Rbuf[(row + 8) * RS + col]     = fmaxf((acc[nt][2] + Rbuf[(row + 8) * RS + col]) * inv1, 0.f);
                Rbuf[(row + 8) * RS + col + 1] = fmaxf((acc[nt][3] + Rbuf[(row + 8) * RS + col + 1]) * inv1, 0.f);
            }
        }
    }
    __syncthreads();

    // ---- final tiny layer + sigmoid ---------------------------------------
    if (tid < MPTS) {
        int gp = p0 + tid;
        float o0 = b_final[0], o1 = b_final[1], o2 = b_final[2], o3 = b_final[3];
#pragma unroll 8
        for (int i = 0; i < 64; i++) {
            float h = Rbuf[tid * RS + i];
            float4 wf = *reinterpret_cast<const float4*>(w_final + i * 4);
            o0 += h * wf.x; o1 += h * wf.y; o2 += h * wf.z; o3 += h * wf.w;
        }
#pragma unroll
        for (int c = 0; c < 3; c++) {
            float dv = d_dir[gp * 3 + c];
            float4 wf = *reinterpret_cast<const float4*>(w_final + (64 + c) * 4);
            o0 += dv * wf.x; o1 += dv * wf.y; o2 += dv * wf.z; o3 += dv * wf.w;
        }
        {
            float tv = d_t[gp];
            float4 wf = *reinterpret_cast<const float4*>(w_final + 67 * 4);
            o0 += tv * wf.x; o1 += tv * wf.y; o2 += tv * wf.z; o3 += tv * wf.w;
        }
        d_out[gp * 4 + 0] = 1.0f / (1.0f + expf(-o0));
        d_out[gp * 4 + 1] = 1.0f / (1.0f + expf(-o1));
        d_out[gp * 4 + 2] = 1.0f / (1.0f + expf(-o2));
        d_out[gp * 4 + 3] = 1.0f / (1.0f + expf(-o3));
    }
}

extern "C" void kernel_launch(void* const* d_in, const int* in_sizes, int n_in,
                              void* d_out, int out_size) {
    const float* pos       = (const float*)d_in[0];
    const float* dirv      = (const float*)d_in[1];
    const float* t         = (const float*)d_in[2];
    const float* table0    = (const float*)d_in[3];
    const float* table1    = (const float*)d_in[4];
    const float* table2    = (const float*)d_in[5];
    const float* table3    = (const float*)d_in[6];
    const float* st1       = (const float*)d_in[7];
    const float* st2       = (const float*)d_in[8];
    const float* tf3       = (const float*)d_in[9];
    const float* rms_scale = (const float*)d_in[10];
    const float* w_down    = (const float*)d_in[11];
    const float* w_final   = (const float*)d_in[12];
    const float* b_final   = (const float*)d_in[13];
    float* out = (float*)d_out;

    wf_precompute_kernel<<<(NK8 * 4 * 32 + 255) / 256, 256>>>(w_down, rms_scale);
    stlt_fused_kernel<<<8192 / MPTS, TPB>>>(
        pos, dirv, t, table0, table1, table2, table3, st1, st2, tf3,
        w_final, b_final, out);
}

// round 9
// speedup vs baseline: 1.6190x; 1.6190x over previous
#include <cuda_runtime.h>
#include <cstdint>

// ---------------------------------------------------------------------------
// Round 8: R7 instruction diet with __launch_bounds__(256,2).
//   R7's (256,3) forced regs 96->80 and spilled into the hot loop (the
//   fewer-instructions-yet-slower signature). Single-line bisect.
// ---------------------------------------------------------------------------

#define MPTS   16
#define TPB    256
#define KC     128
#define KPAD   12288
#define NCH    (KPAD / KC)
#define SA     132            // A smem row stride (u32)
#define RS     72             // reduce buffer row stride (floats)
#define NK8    (KPAD / 8)     // 1536
#define NB     172            // base-table entries per point

__device__ uint4 g_Wf4[NK8 * 4 * 32];  // [(K8*4 + nt2)*32 + lane] = {b0e,b1e,b0o,b1o}

__constant__ int c_OFF7[7][3] = {
    {0,0,0},{1,0,0},{-1,0,0},{0,1,0},{0,-1,0},{0,0,1},{0,0,-1}};
__constant__ int c_S14[14][3] = {
    {1,0,0},{-1,0,0},{0,1,0},{0,-1,0},{0,0,1},{0,0,-1},
    {1,1,1},{-1,-1,-1},{1,-1,-1},{-1,1,1},{1,1,-1},{-1,-1,1},{1,-1,1},{-1,1,-1}};
__constant__ int c_CORNER[8][3] = {
    {1,1,1},{-1,-1,-1},{1,-1,-1},{-1,1,1},{1,1,-1},{-1,-1,1},{1,-1,1},{-1,1,-1}};
__constant__ int c_ETEMP[11] = {-64,-8,-4,-2,-1,0,1,2,4,8,64};

__device__ __forceinline__ uint32_t f2tf32(float x) {
    uint32_t u;
    asm("cvt.rna.tf32.f32 %0, %1;" : "=r"(u) : "f"(x));
    return u;
}

__device__ __forceinline__ uint32_t s2u(const void* p) {
    uint32_t a;
    asm("{ .reg .u64 t; cvta.to.shared.u64 t, %1; cvt.u32.u64 %0, t; }"
        : "=r"(a) : "l"(p));
    return a;
}

__device__ __forceinline__ void mma8(float* c,
                                     uint32_t a0, uint32_t a1, uint32_t a2, uint32_t a3,
                                     uint32_t b0, uint32_t b1) {
    asm("mma.sync.aligned.m16n8k8.row.col.f32.tf32.tf32.f32 "
        "{%0,%1,%2,%3}, {%4,%5,%6,%7}, {%8,%9}, {%0,%1,%2,%3};"
        : "+f"(c[0]), "+f"(c[1]), "+f"(c[2]), "+f"(c[3])
        : "r"(a0), "r"(a1), "r"(a2), "r"(a3), "r"(b0), "r"(b1));
}

// ---------------------------------------------------------------------------
__global__ void __launch_bounds__(256)
wf_precompute_kernel(const float* __restrict__ w_down,
                     const float* __restrict__ rms_scale)
{
    int T = blockIdx.x * 256 + threadIdx.x;
    if (T >= NK8 * 4 * 32) return;
    int lane = T & 31;
    int nt2  = (T >> 5) & 3;
    int K8   = T >> 7;
    int ne = nt2 * 16 + (lane >> 2);
    int no = ne + 8;
    int k0 = K8 * 8 + (lane & 3);
    int k1 = k0 + 4;
    uint4 u;
    u.x = (k0 < 12240) ? f2tf32(w_down[k0 * 64 + ne] * rms_scale[k0]) : 0u;
    u.y = (k1 < 12240) ? f2tf32(w_down[k1 * 64 + ne] * rms_scale[k1]) : 0u;
    u.z = (k0 < 12240) ? f2tf32(w_down[k0 * 64 + no] * rms_scale[k0]) : 0u;
    u.w = (k1 < 12240) ? f2tf32(w_down[k1 * 64 + no] * rms_scale[k1]) : 0u;
    g_Wf4[T] = u;
}

// ---------------------------------------------------------------------------
// Gather 4 consecutive features via precomputed per-point base table.
__device__ __forceinline__ float4 gather4b(
    int k, const int* __restrict__ bp,
    const float* __restrict__ T0, const float* __restrict__ T1,
    const float* __restrict__ T2, const float* __restrict__ T3,
    const float* __restrict__ S1t, const float* __restrict__ S2t,
    const float* __restrict__ TF)
{
    if (k < 9520) {
        const float* tab; int r, flog, bi;
        if (k < 112)       { tab = T0; r = k;        flog = 4;  bi = 0;  }
        else if (k < 560)  { tab = T1; r = k - 112;  flog = 6;  bi = 7;  }
        else if (k < 2352) { tab = T2; r = k - 560;  flog = 8;  bi = 14; }
        else               { tab = T3; r = k - 2352; flog = 10; bi = 21; }
        int o = r >> flog;
        int f = r & ((1 << flog) - 1);
        return *reinterpret_cast<const float4*>(tab + bp[bi + o] + f);
    }
    if (k < 11312) {
        int r = k - 9520;
        return *reinterpret_cast<const float4*>(S1t + bp[28 + (r >> 6)] + (r & 63));
    }
    if (k < 11536) {
        int r = k - 11312;
        return *reinterpret_cast<const float4*>(S2t + bp[56 + (r >> 3)] + (r & 7));
    }
    if (k < 12240) {
        int r = k - 11536;
        return *reinterpret_cast<const float4*>(TF + bp[84 + (r >> 3)] + (r & 7));
    }
    return make_float4(0.f, 0.f, 0.f, 0.f);
}

// ---------------------------------------------------------------------------
__global__ void __launch_bounds__(TPB, 2)
stlt_fused_kernel(
    const float* __restrict__ d_pos, const float* __restrict__ d_dir,
    const float* __restrict__ d_t,
    const float* __restrict__ T0, const float* __restrict__ T1,
    const float* __restrict__ T2, const float* __restrict__ T3,
    const float* __restrict__ S1t, const float* __restrict__ S2t,
    const float* __restrict__ TF,
    const float* __restrict__ w_final, const float* __restrict__ b_final,
    float* __restrict__ d_out)
{
    __shared__ alignas(16) uint32_t As[2 * MPTS * SA];   // double-buffered A
    __shared__ alignas(16) float    Rbuf[MPTS * RS];
    __shared__ int      bases[MPTS * NB];
    __shared__ int      pidx[MPTS][14];
    __shared__ float    sumsq_s[MPTS];

    const int tid  = threadIdx.x;
    const int lane = tid & 31;
    const int warp = tid >> 5;
    const int kq   = warp >> 1;     // k-quarter 0..3
    const int nh   = warp & 1;      // n-half 0..1 (cols [nh*32, +32))
    const int p0   = blockIdx.x * MPTS;

    if (tid < MPTS) {
        int gp = p0 + tid;
        float px = d_pos[gp * 3 + 0];
        float py = d_pos[gp * 3 + 1];
        float pz = d_pos[gp * 3 + 2];
        pidx[tid][0]  = (int)(px * 127.0f);
        pidx[tid][1]  = (int)(py * 127.0f);
        pidx[tid][2]  = (int)(pz * 127.0f);
        pidx[tid][3]  = (int)(px * 63.0f);
        pidx[tid][4]  = (int)(py * 63.0f);
        pidx[tid][5]  = (int)(pz * 63.0f);
        pidx[tid][6]  = (int)(px * 31.0f);
        pidx[tid][7]  = (int)(py * 31.0f);
        pidx[tid][8]  = (int)(pz * 31.0f);
        pidx[tid][9]  = (int)(px * 15.0f);
        pidx[tid][10] = (int)(py * 15.0f);
        pidx[tid][11] = (int)(pz * 15.0f);
        float tv = d_t[gp];
        pidx[tid][12] = (int)(tv * 15.0f);
        pidx[tid][13] = (int)(tv * 63.0f);
    }
    __syncthreads();

    // ---- fill per-point base-address table (element offsets) --------------
    for (int e = tid; e < MPTS * NB; e += TPB) {
        int p = e / NB;
        int j = e - p * NB;
        int b;
        if (j < 28) {                       // spatial: tau = j/7, o = j%7
            int tau  = j / 7;
            int o    = j - tau * 7;
            int dlog = 7 - tau;
            int flog = 4 + 2 * tau;
            int d = 1 << dlog, m = d - 1;
            int cx = (pidx[p][tau * 3 + 0] + c_OFF7[o][0] + d) & m;
            int cy = (pidx[p][tau * 3 + 1] + c_OFF7[o][1] + d) & m;
            int cz = (pidx[p][tau * 3 + 2] + c_OFF7[o][2] + d) & m;
            b = ((((cx << dlog) | cy) << dlog) | cz) << flog;
        } else if (j < 56) {                // st1 (16,16,16,64) F=64
            int jj = j - 28;
            int si = jj >> 1;
            int tt = (jj & 1) ? -1 : 1;
            int tb = pidx[p][12], tv = pidx[p][13];
            int a  = (tb + c_S14[si][0] + 16) & 15;
            int bb = (tb + c_S14[si][1] + 16) & 15;
            int c  = (tb + c_S14[si][2] + 16) & 15;
            int dd = (tv + tt + 64) & 63;
            b = ((((((a << 4) | bb) << 4) | c) << 6) | dd) << 6;
        } else if (j < 84) {                // st2 (64,64,64,64) F=8
            int jj = j - 56;
            int si = jj >> 1;
            int tt = (jj & 1) ? -1 : 1;
            int tb = pidx[p][12], tv = pidx[p][13];
            int a  = (tb + c_S14[si][0] + 64) & 63;
            int bb = (tb + c_S14[si][1] + 64) & 63;
            int c  = (tb + c_S14[si][2] + 64) & 63;
            int dd = (tv + tt + 64) & 63;
            b = ((((((a << 6) | bb) << 6) | c) << 6) | dd) << 3;
        } else {                            // tf3 (4,4,4,65536) F=8
            int jj = j - 84;
            int ci = jj / 11;
            int ti = jj - ci * 11;
            int tb = pidx[p][12], tv = pidx[p][13];
            int a  = (tb + c_CORNER[ci][0] + 4) & 3;
            int bb = (tb + c_CORNER[ci][1] + 4) & 3;
            int c  = (tb + c_CORNER[ci][2] + 4) & 3;
            int dd = (tv + c_ETEMP[ti] + 65536) & 65535;
            b = ((((((a << 2) | bb) << 2) | c) << 16) | dd) << 3;
        }
        bases[e] = b;
    }
    __syncthreads();

    float acc[4][4];
#pragma unroll
    for (int i = 0; i < 4; i++)
#pragma unroll
        for (int j = 0; j < 4; j++) acc[i][j] = 0.f;
    // per-thread sumsq: this thread only ever touches points {warp, warp+8}
    float ss0 = 0.f, ss1 = 0.f;

    const int lm_row = ((lane >> 3) & 1) * 8 + (lane & 7);
    const int lm_kof = (lane >> 4) * 4;

    // ---- prologue: gather chunk 0 into regs (2 float4 per thread) ---------
    float4 v[2];
#pragma unroll
    for (int j = 0; j < 2; j++) {
        int i  = tid + j * TPB;
        int p  = i >> 5;
        int k4 = (i & 31) << 2;
        v[j] = gather4b(k4, bases + p * NB, T0, T1, T2, T3, S1t, S2t, TF);
    }

    for (int ch = 0; ch < NCH; ch++) {
        uint32_t* buf = As + (ch & 1) * (MPTS * SA);
        const int kb  = ch * KC;

        // ---- STS: relu + per-thread sumsq + store raw fp32 bits ----------
        {
            float4 w0 = v[0];
            w0.x = fmaxf(w0.x, 0.f); w0.y = fmaxf(w0.y, 0.f);
            w0.z = fmaxf(w0.z, 0.f); w0.w = fmaxf(w0.w, 0.f);
            ss0 += w0.x * w0.x + w0.y * w0.y + w0.z * w0.z + w0.w * w0.w;
            float4 w1 = v[1];
            w1.x = fmaxf(w1.x, 0.f); w1.y = fmaxf(w1.y, 0.f);
            w1.z = fmaxf(w1.z, 0.f); w1.w = fmaxf(w1.w, 0.f);
            ss1 += w1.x * w1.x + w1.y * w1.y + w1.z * w1.z + w1.w * w1.w;
            int i0 = tid;
            int i1 = tid + TPB;
            *reinterpret_cast<float4*>(&buf[(i0 >> 5) * SA + ((i0 & 31) << 2)]) = w0;
            *reinterpret_cast<float4*>(&buf[(i1 >> 5) * SA + ((i1 & 31) << 2)]) = w1;
        }
        __syncthreads();

        // ---- prefetch next chunk (overlaps mma) ---------------------------
        if (ch + 1 < NCH) {
#pragma unroll
            for (int j = 0; j < 2; j++) {
                int i  = tid + j * TPB;
                int p  = i >> 5;
                int k4 = (i & 31) << 2;
                v[j] = gather4b(kb + KC + k4, bases + p * NB, T0, T1, T2, T3, S1t, S2t, TF);
            }
        }

        // ---- mma: warp covers k8 in [kq*4, +4), n [nh*32, +32) ------------
        // fp32 bits fed directly to tf32 mma (HW truncates low mantissa).
#pragma unroll
        for (int g = 0; g < 4; g++) {
            int K8l = kq * 4 + g;
            int kk  = K8l * 8;
            uint32_t a0, a1, a2, a3;
            uint32_t addr = s2u(&buf[lm_row * SA + kk + lm_kof]);
            asm volatile("ldmatrix.sync.aligned.m8n8.x4.shared.b16 {%0,%1,%2,%3}, [%4];"
                         : "=r"(a0), "=r"(a1), "=r"(a2), "=r"(a3) : "r"(addr));
            const uint4* Wk = g_Wf4 + ((size_t)(ch * 16 + K8l) << 7) + lane;
#pragma unroll
            for (int q = 0; q < 2; q++) {
                uint4 bq = Wk[(2 * nh + q) * 32];
                mma8(acc[2 * q],     a0, a1, a2, a3, bq.x, bq.y);
                mma8(acc[2 * q + 1], a0, a1, a2, a3, bq.z, bq.w);
            }
        }
    }

    // ---- sumsq: warp-wide reduce, single writer per point -----------------
#pragma unroll
    for (int s = 16; s >= 1; s >>= 1) {
        ss0 += __shfl_xor_sync(0xffffffffu, ss0, s);
        ss1 += __shfl_xor_sync(0xffffffffu, ss1, s);
    }
    if (lane == 0) {
        sumsq_s[warp]     = ss0;   // point index = warp   (i0>>5 == warp)
        sumsq_s[warp + 8] = ss1;   // point index = warp+8 (i1>>5 == warp+8)
    }

    // ---- cross-k acc reduction (serialized by kq; both nh in parallel) ----
    {
        int row = lane >> 2;
        int cb  = nh * 32 + (lane & 3) * 2;
        if (kq == 3) {
#pragma unroll
            for (int nt = 0; nt < 4; nt++) {
                int col = cb + nt * 8;
                Rbuf[row * RS + col]           = acc[nt][0];
                Rbuf[row * RS + col + 1]       = acc[nt][1];
                Rbuf[(row + 8) * RS + col]     = acc[nt][2];
                Rbuf[(row + 8) * RS + col + 1] = acc[nt][3];
            }
        }
        __syncthreads();
        if (kq == 2) {
#pragma unroll
            for (int nt = 0; nt < 4; nt++) {
                int col = cb + nt * 8;
                Rbuf[row * RS + col]           += acc[nt][0];
                Rbuf[row * RS + col + 1]       += acc[nt][1];
                Rbuf[(row + 8) * RS + col]     += acc[nt][2];
                Rbuf[(row + 8) * RS + col + 1] += acc[nt][3];
            }
        }
        __syncthreads();
        if (kq == 1) {
#pragma unroll
            for (int nt = 0; nt < 4; nt++) {
                int col = cb + nt * 8;
                Rbuf[row * RS + col]           += acc[nt][0];
                Rbuf[row * RS + col + 1]       += acc[nt][1];
                Rbuf[(row + 8) * RS + col]     += acc[nt][2];
                Rbuf[(row + 8) * RS + col + 1] += acc[nt][3];
            }
        }
        __syncthreads();
        if (kq == 0) {
            float inv0 = 1.0f / (sqrtf(sumsq_s[row] * (1.0f / 12240.0f)) + 1e-8f);
            float inv1 = 1.0f / (sqrtf(sumsq_s[row + 8] * (1.0f / 12240.0f)) + 1e-8f);
#pragma unroll
            for (int nt = 0; nt < 4; nt++) {
                int col = cb + nt * 8;
                Rbuf[row * RS + col]           = fmaxf((acc[nt][0] + Rbuf[row * RS + col]) * inv0, 0.f);
                Rbuf[row * RS + col + 1]       = fmaxf((acc[nt][1] + Rbuf[row * RS + col + 1]) * inv0, 0.f);
                Rbuf[(row + 8) * RS + col]     = fmaxf((acc[nt][2] + Rbuf[(row + 8) * RS + col]) * inv1, 0.f);
                Rbuf[(row + 8) * RS + col + 1] = fmaxf((acc[nt][3] + Rbuf[(row + 8) * RS + col + 1]) * inv1, 0.f);
            }
        }
    }
    __syncthreads();

    // ---- final tiny layer + sigmoid ---------------------------------------
    if (tid < MPTS) {
        int gp = p0 + tid;
        float o0 = b_final[0], o1 = b_final[1], o2 = b_final[2], o3 = b_final[3];
#pragma unroll 8
        for (int i = 0; i < 64; i++) {
            float h = Rbuf[tid * RS + i];
            float4 wf = *reinterpret_cast<const float4*>(w_final + i * 4);
            o0 += h * wf.x; o1 += h * wf.y; o2 += h * wf.z; o3 += h * wf.w;
        }
#pragma unroll
        for (int c = 0; c < 3; c++) {
            float dv = d_dir[gp * 3 + c];
            float4 wf = *reinterpret_cast<const float4*>(w_final + (64 + c) * 4);
            o0 += dv * wf.x; o1 += dv * wf.y; o2 += dv * wf.z; o3 += dv * wf.w;
        }
        {
            float tv = d_t[gp];
            float4 wf = *reinterpret_cast<const float4*>(w_final + 67 * 4);
            o0 += tv * wf.x; o1 += tv * wf.y; o2 += tv * wf.z; o3 += tv * wf.w;
        }
        d_out[gp * 4 + 0] = 1.0f / (1.0f + expf(-o0));
        d_out[gp * 4 + 1] = 1.0f / (1.0f + expf(-o1));
        d_out[gp * 4 + 2] = 1.0f / (1.0f + expf(-o2));
        d_out[gp * 4 + 3] = 1.0f / (1.0f + expf(-o3));
    }
}

extern "C" void kernel_launch(void* const* d_in, const int* in_sizes, int n_in,
                              void* d_out, int out_size) {
    const float* pos       = (const float*)d_in[0];
    const float* dirv      = (const float*)d_in[1];
    const float* t         = (const float*)d_in[2];
    const float* table0    = (const float*)d_in[3];
    const float* table1    = (const float*)d_in[4];
    const float* table2    = (const float*)d_in[5];
    const float* table3    = (const float*)d_in[6];
    const float* st1       = (const float*)d_in[7];
    const float* st2       = (const float*)d_in[8];
    const float* tf3       = (const float*)d_in[9];
    const float* rms_scale = (const float*)d_in[10];
    const float* w_down    = (const float*)d_in[11];
    const float* w_final   = (const float*)d_in[12];
    const float* b_final   = (const float*)d_in[13];
    float* out = (float*)d_out;

    wf_precompute_kernel<<<(NK8 * 4 * 32 + 255) / 256, 256>>>(w_down, rms_scale);
    stlt_fused_kernel<<<8192 / MPTS, TPB>>>(
        pos, dirv, t, table0, table1, table2, table3, st1, st2, tf3,
        w_final, b_final, out);
}

// round 10
// speedup vs baseline: 2.0686x; 1.2777x over previous
#include <cuda_runtime.h>
#include <cstdint>

// ---------------------------------------------------------------------------
// Round 9: MPTS 16 -> 32 (m32 x n64 CTA tile). Halves B-fragment L2 traffic
//   (3 MB stream amortized over 2x points), halves barriers per point, and
//   doubles independent mma work per B load. acc 2x4x4, v[4].
// ---------------------------------------------------------------------------

#define MPTS   32
#define TPB    256
#define KC     128
#define KPAD   12288
#define NCH    (KPAD / KC)
#define SA     132            // A smem row stride (u32)
#define RS     72             // reduce buffer row stride (floats)
#define NK8    (KPAD / 8)     // 1536
#define NB     172            // base-table entries per point

__device__ uint4 g_Wf4[NK8 * 4 * 32];  // [(K8*4 + nt2)*32 + lane] = {b0e,b1e,b0o,b1o}

__constant__ int c_OFF7[7][3] = {
    {0,0,0},{1,0,0},{-1,0,0},{0,1,0},{0,-1,0},{0,0,1},{0,0,-1}};
__constant__ int c_S14[14][3] = {
    {1,0,0},{-1,0,0},{0,1,0},{0,-1,0},{0,0,1},{0,0,-1},
    {1,1,1},{-1,-1,-1},{1,-1,-1},{-1,1,1},{1,1,-1},{-1,-1,1},{1,-1,1},{-1,1,-1}};
__constant__ int c_CORNER[8][3] = {
    {1,1,1},{-1,-1,-1},{1,-1,-1},{-1,1,1},{1,1,-1},{-1,-1,1},{1,-1,1},{-1,1,-1}};
__constant__ int c_ETEMP[11] = {-64,-8,-4,-2,-1,0,1,2,4,8,64};

__device__ __forceinline__ uint32_t f2tf32(float x) {
    uint32_t u;
    asm("cvt.rna.tf32.f32 %0, %1;" : "=r"(u) : "f"(x));
    return u;
}

__device__ __forceinline__ uint32_t s2u(const void* p) {
    uint32_t a;
    asm("{ .reg .u64 t; cvta.to.shared.u64 t, %1; cvt.u32.u64 %0, t; }"
        : "=r"(a) : "l"(p));
    return a;
}

__device__ __forceinline__ void mma8(float* c,
                                     uint32_t a0, uint32_t a1, uint32_t a2, uint32_t a3,
                                     uint32_t b0, uint32_t b1) {
    asm("mma.sync.aligned.m16n8k8.row.col.f32.tf32.tf32.f32 "
        "{%0,%1,%2,%3}, {%4,%5,%6,%7}, {%8,%9}, {%0,%1,%2,%3};"
        : "+f"(c[0]), "+f"(c[1]), "+f"(c[2]), "+f"(c[3])
        : "r"(a0), "r"(a1), "r"(a2), "r"(a3), "r"(b0), "r"(b1));
}

// ---------------------------------------------------------------------------
__global__ void __launch_bounds__(256)
wf_precompute_kernel(const float* __restrict__ w_down,
                     const float* __restrict__ rms_scale)
{
    int T = blockIdx.x * 256 + threadIdx.x;
    if (T >= NK8 * 4 * 32) return;
    int lane = T & 31;
    int nt2  = (T >> 5) & 3;
    int K8   = T >> 7;
    int ne = nt2 * 16 + (lane >> 2);
    int no = ne + 8;
    int k0 = K8 * 8 + (lane & 3);
    int k1 = k0 + 4;
    uint4 u;
    u.x = (k0 < 12240) ? f2tf32(w_down[k0 * 64 + ne] * rms_scale[k0]) : 0u;
    u.y = (k1 < 12240) ? f2tf32(w_down[k1 * 64 + ne] * rms_scale[k1]) : 0u;
    u.z = (k0 < 12240) ? f2tf32(w_down[k0 * 64 + no] * rms_scale[k0]) : 0u;
    u.w = (k1 < 12240) ? f2tf32(w_down[k1 * 64 + no] * rms_scale[k1]) : 0u;
    g_Wf4[T] = u;
}

// ---------------------------------------------------------------------------
// Gather 4 consecutive features via precomputed per-point base table.
__device__ __forceinline__ float4 gather4b(
    int k, const int* __restrict__ bp,
    const float* __restrict__ T0, const float* __restrict__ T1,
    const float* __restrict__ T2, const float* __restrict__ T3,
    const float* __restrict__ S1t, const float* __restrict__ S2t,
    const float* __restrict__ TF)
{
    if (k < 9520) {
        const float* tab; int r, flog, bi;
        if (k < 112)       { tab = T0; r = k;        flog = 4;  bi = 0;  }
        else if (k < 560)  { tab = T1; r = k - 112;  flog = 6;  bi = 7;  }
        else if (k < 2352) { tab = T2; r = k - 560;  flog = 8;  bi = 14; }
        else               { tab = T3; r = k - 2352; flog = 10; bi = 21; }
        int o = r >> flog;
        int f = r & ((1 << flog) - 1);
        return *reinterpret_cast<const float4*>(tab + bp[bi + o] + f);
    }
    if (k < 11312) {
        int r = k - 9520;
        return *reinterpret_cast<const float4*>(S1t + bp[28 + (r >> 6)] + (r & 63));
    }
    if (k < 11536) {
        int r = k - 11312;
        return *reinterpret_cast<const float4*>(S2t + bp[56 + (r >> 3)] + (r & 7));
    }
    if (k < 12240) {
        int r = k - 11536;
        return *reinterpret_cast<const float4*>(TF + bp[84 + (r >> 3)] + (r & 7));
    }
    return make_float4(0.f, 0.f, 0.f, 0.f);
}

// ---------------------------------------------------------------------------
__global__ void __launch_bounds__(TPB, 2)
stlt_fused_kernel(
    const float* __restrict__ d_pos, const float* __restrict__ d_dir,
    const float* __restrict__ d_t,
    const float* __restrict__ T0, const float* __restrict__ T1,
    const float* __restrict__ T2, const float* __restrict__ T3,
    const float* __restrict__ S1t, const float* __restrict__ S2t,
    const float* __restrict__ TF,
    const float* __restrict__ w_final, const float* __restrict__ b_final,
    float* __restrict__ d_out)
{
    __shared__ alignas(16) uint32_t As[2 * MPTS * SA];   // double-buffered A
    __shared__ alignas(16) float    Rbuf[MPTS * RS];
    __shared__ int      bases[MPTS * NB];
    __shared__ int      pidx[MPTS][14];
    __shared__ float    sumsq_s[MPTS];

    const int tid  = threadIdx.x;
    const int lane = tid & 31;
    const int warp = tid >> 5;
    const int kq   = warp >> 1;     // k-quarter 0..3
    const int nh   = warp & 1;      // n-half 0..1 (cols [nh*32, +32))
    const int p0   = blockIdx.x * MPTS;

    if (tid < MPTS) {
        int gp = p0 + tid;
        float px = d_pos[gp * 3 + 0];
        float py = d_pos[gp * 3 + 1];
        float pz = d_pos[gp * 3 + 2];
        pidx[tid][0]  = (int)(px * 127.0f);
        pidx[tid][1]  = (int)(py * 127.0f);
        pidx[tid][2]  = (int)(pz * 127.0f);
        pidx[tid][3]  = (int)(px * 63.0f);
        pidx[tid][4]  = (int)(py * 63.0f);
        pidx[tid][5]  = (int)(pz * 63.0f);
        pidx[tid][6]  = (int)(px * 31.0f);
        pidx[tid][7]  = (int)(py * 31.0f);
        pidx[tid][8]  = (int)(pz * 31.0f);
        pidx[tid][9]  = (int)(px * 15.0f);
        pidx[tid][10] = (int)(py * 15.0f);
        pidx[tid][11] = (int)(pz * 15.0f);
        float tv = d_t[gp];
        pidx[tid][12] = (int)(tv * 15.0f);
        pidx[tid][13] = (int)(tv * 63.0f);
    }
    __syncthreads();

    // ---- fill per-point base-address table (element offsets) --------------
    for (int e = tid; e < MPTS * NB; e += TPB) {
        int p = e / NB;
        int j = e - p * NB;
        int b;
        if (j < 28) {                       // spatial: tau = j/7, o = j%7
            int tau  = j / 7;
            int o    = j - tau * 7;
            int dlog = 7 - tau;
            int flog = 4 + 2 * tau;
            int d = 1 << dlog, m = d - 1;
            int cx = (pidx[p][tau * 3 + 0] + c_OFF7[o][0] + d) & m;
            int cy = (pidx[p][tau * 3 + 1] + c_OFF7[o][1] + d) & m;
            int cz = (pidx[p][tau * 3 + 2] + c_OFF7[o][2] + d) & m;
            b = ((((cx << dlog) | cy) << dlog) | cz) << flog;
        } else if (j < 56) {                // st1 (16,16,16,64) F=64
            int jj = j - 28;
            int si = jj >> 1;
            int tt = (jj & 1) ? -1 : 1;
            int tb = pidx[p][12], tv = pidx[p][13];
            int a  = (tb + c_S14[si][0] + 16) & 15;
            int bb = (tb + c_S14[si][1] + 16) & 15;
            int c  = (tb + c_S14[si][2] + 16) & 15;
            int dd = (tv + tt + 64) & 63;
            b = ((((((a << 4) | bb) << 4) | c) << 6) | dd) << 6;
        } else if (j < 84) {                // st2 (64,64,64,64) F=8
            int jj = j - 56;
            int si = jj >> 1;
            int tt = (jj & 1) ? -1 : 1;
            int tb = pidx[p][12], tv = pidx[p][13];
            int a  = (tb + c_S14[si][0] + 64) & 63;
            int bb = (tb + c_S14[si][1] + 64) & 63;
            int c  = (tb + c_S14[si][2] + 64) & 63;
            int dd = (tv + tt + 64) & 63;
            b = ((((((a << 6) | bb) << 6) | c) << 6) | dd) << 3;
        } else {                            // tf3 (4,4,4,65536) F=8
            int jj = j - 84;
            int ci = jj / 11;
            int ti = jj - ci * 11;
            int tb = pidx[p][12], tv = pidx[p][13];
            int a  = (tb + c_CORNER[ci][0] + 4) & 3;
            int bb = (tb + c_CORNER[ci][1] + 4) & 3;
            int c  = (tb + c_CORNER[ci][2] + 4) & 3;
            int dd = (tv + c_ETEMP[ti] + 65536) & 65535;
            b = ((((((a << 2) | bb) << 2) | c) << 16) | dd) << 3;
        }
        bases[e] = b;
    }
    __syncthreads();

    float acc[2][4][4];
#pragma unroll
    for (int m = 0; m < 2; m++)
#pragma unroll
        for (int i = 0; i < 4; i++)
#pragma unroll
            for (int j = 0; j < 4; j++) acc[m][i][j] = 0.f;
    // per-thread sumsq: thread in warp w touches points {w, w+8, w+16, w+24}
    float ss[4] = {0.f, 0.f, 0.f, 0.f};

    const int lm_row = ((lane >> 3) & 1) * 8 + (lane & 7);
    const int lm_kof = (lane >> 4) * 4;

    // ---- prologue: gather chunk 0 into regs (4 float4 per thread) ---------
    float4 v[4];
#pragma unroll
    for (int j = 0; j < 4; j++) {
        int i  = tid + j * TPB;
        int p  = i >> 5;
        int k4 = (i & 31) << 2;
        v[j] = gather4b(k4, bases + p * NB, T0, T1, T2, T3, S1t, S2t, TF);
    }

    for (int ch = 0; ch < NCH; ch++) {
        uint32_t* buf = As + (ch & 1) * (MPTS * SA);
        const int kb  = ch * KC;

        // ---- STS: relu + per-thread sumsq + store raw fp32 bits ----------
#pragma unroll
        for (int j = 0; j < 4; j++) {
            float4 w = v[j];
            w.x = fmaxf(w.x, 0.f); w.y = fmaxf(w.y, 0.f);
            w.z = fmaxf(w.z, 0.f); w.w = fmaxf(w.w, 0.f);
            ss[j] += w.x * w.x + w.y * w.y + w.z * w.z + w.w * w.w;
            int i = tid + j * TPB;
            *reinterpret_cast<float4*>(&buf[(i >> 5) * SA + ((i & 31) << 2)]) = w;
        }
        __syncthreads();

        // ---- prefetch next chunk (overlaps mma) ---------------------------
        if (ch + 1 < NCH) {
#pragma unroll
            for (int j = 0; j < 4; j++) {
                int i  = tid + j * TPB;
                int p  = i >> 5;
                int k4 = (i & 31) << 2;
                v[j] = gather4b(kb + KC + k4, bases + p * NB, T0, T1, T2, T3, S1t, S2t, TF);
            }
        }

        // ---- mma: warp covers k8 in [kq*4, +4), n [nh*32, +32), m all 32 --
#pragma unroll
        for (int g = 0; g < 4; g++) {
            int K8l = kq * 4 + g;
            int kk  = K8l * 8;
            const uint4* Wk = g_Wf4 + ((size_t)(ch * 16 + K8l) << 7) + lane;
            uint4 bq0 = Wk[(2 * nh) * 32];
            uint4 bq1 = Wk[(2 * nh + 1) * 32];
#pragma unroll
            for (int mt = 0; mt < 2; mt++) {
                uint32_t a0, a1, a2, a3;
                uint32_t addr = s2u(&buf[(mt * 16 + lm_row) * SA + kk + lm_kof]);
                asm volatile("ldmatrix.sync.aligned.m8n8.x4.shared.b16 {%0,%1,%2,%3}, [%4];"
                             : "=r"(a0), "=r"(a1), "=r"(a2), "=r"(a3) : "r"(addr));
                mma8(acc[mt][0], a0, a1, a2, a3, bq0.x, bq0.y);
                mma8(acc[mt][1], a0, a1, a2, a3, bq0.z, bq0.w);
                mma8(acc[mt][2], a0, a1, a2, a3, bq1.x, bq1.y);
                mma8(acc[mt][3], a0, a1, a2, a3, bq1.z, bq1.w);
            }
        }
    }

    // ---- sumsq: warp-wide reduce, single writer per point -----------------
#pragma unroll
    for (int s = 16; s >= 1; s >>= 1) {
#pragma unroll
        for (int j = 0; j < 4; j++)
            ss[j] += __shfl_xor_sync(0xffffffffu, ss[j], s);
    }
    if (lane == 0) {
#pragma unroll
        for (int j = 0; j < 4; j++)
            sumsq_s[warp + 8 * j] = ss[j];   // point index = (tid + j*TPB)>>5
    }

    // ---- cross-k acc reduction (serialized by kq; both nh in parallel) ----
    {
        int row = lane >> 2;
        int cb  = nh * 32 + (lane & 3) * 2;
        if (kq == 3) {
#pragma unroll
            for (int mt = 0; mt < 2; mt++)
#pragma unroll
            for (int nt = 0; nt < 4; nt++) {
                int col = cb + nt * 8;
                int r0 = mt * 16 + row;
                Rbuf[r0 * RS + col]           = acc[mt][nt][0];
                Rbuf[r0 * RS + col + 1]       = acc[mt][nt][1];
                Rbuf[(r0 + 8) * RS + col]     = acc[mt][nt][2];
                Rbuf[(r0 + 8) * RS + col + 1] = acc[mt][nt][3];
            }
        }
        __syncthreads();
        if (kq == 2) {
#pragma unroll
            for (int mt = 0; mt < 2; mt++)
#pragma unroll
            for (int nt = 0; nt < 4; nt++) {
                int col = cb + nt * 8;
                int r0 = mt * 16 + row;
                Rbuf[r0 * RS + col]           += acc[mt][nt][0];
                Rbuf[r0 * RS + col + 1]       += acc[mt][nt][1];
                Rbuf[(r0 + 8) * RS + col]     += acc[mt][nt][2];
                Rbuf[(r0 + 8) * RS + col + 1] += acc[mt][nt][3];
            }
        }
        __syncthreads();
        if (kq == 1) {
#pragma unroll
            for (int mt = 0; mt < 2; mt++)
#pragma unroll
            for (int nt = 0; nt < 4; nt++) {
                int col = cb + nt * 8;
                int r0 = mt * 16 + row;
                Rbuf[r0 * RS + col]           += acc[mt][nt][0];
                Rbuf[r0 * RS + col + 1]       += acc[mt][nt][1];
                Rbuf[(r0 + 8) * RS + col]     += acc[mt][nt][2];
                Rbuf[(r0 + 8) * RS + col + 1] += acc[mt][nt][3];
            }
        }
        __syncthreads();
        if (kq == 0) {
#pragma unroll
            for (int mt = 0; mt < 2; mt++) {
                int r0 = mt * 16 + row;
                float inv0 = 1.0f / (sqrtf(sumsq_s[r0] * (1.0f / 12240.0f)) + 1e-8f);
                float inv1 = 1.0f / (sqrtf(sumsq_s[r0 + 8] * (1.0f / 12240.0f)) + 1e-8f);
#pragma unroll
                for (int nt = 0; nt < 4; nt++) {
                    int col = cb + nt * 8;
                    Rbuf[r0 * RS + col]           = fmaxf((acc[mt][nt][0] + Rbuf[r0 * RS + col]) * inv0, 0.f);
                    Rbuf[r0 * RS + col + 1]       = fmaxf((acc[mt][nt][1] + Rbuf[r0 * RS + col + 1]) * inv0, 0.f);
                    Rbuf[(r0 + 8) * RS + col]     = fmaxf((acc[mt][nt][2] + Rbuf[(r0 + 8) * RS + col]) * inv1, 0.f);
                    Rbuf[(r0 + 8) * RS + col + 1] = fmaxf((acc[mt][nt][3] + Rbuf[(r0 + 8) * RS + col + 1]) * inv1, 0.f);
                }
            }
        }
    }
    __syncthreads();

    // ---- final tiny layer + sigmoid ---------------------------------------
    if (tid < MPTS) {
        int gp = p0 + tid;
        float o0 = b_final[0], o1 = b_final[1], o2 = b_final[2], o3 = b_final[3];
#pragma unroll 8
        for (int i = 0; i < 64; i++) {
            float h = Rbuf[tid * RS + i];
            float4 wf = *reinterpret_cast<const float4*>(w_final + i * 4);
            o0 += h * wf.x; o1 += h * wf.y; o2 += h * wf.z; o3 += h * wf.w;
        }
#pragma unroll
        for (int c = 0; c < 3; c++) {
            float dv = d_dir[gp * 3 + c];
            float4 wf = *reinterpret_cast<const float4*>(w_final + (64 + c) * 4);
            o0 += dv * wf.x; o1 += dv * wf.y; o2 += dv * wf.z; o3 += dv * wf.w;
        }
        {
            float tv = d_t[gp];
            float4 wf = *reinterpret_cast<const float4*>(w_final + 67 * 4);
            o0 += tv * wf.x; o1 += tv * wf.y; o2 += tv * wf.z; o3 += tv * wf.w;
        }
        d_out[gp * 4 + 0] = 1.0f / (1.0f + expf(-o0));
        d_out[gp * 4 + 1] = 1.0f / (1.0f + expf(-o1));
        d_out[gp * 4 + 2] = 1.0f / (1.0f + expf(-o2));
        d_out[gp * 4 + 3] = 1.0f / (1.0f + expf(-o3));
    }
}

extern "C" void kernel_launch(void* const* d_in, const int* in_sizes, int n_in,
                              void* d_out, int out_size) {
    const float* pos       = (const float*)d_in[0];
    const float* dirv      = (const float*)d_in[1];
    const float* t         = (const float*)d_in[2];
    const float* table0    = (const float*)d_in[3];
    const float* table1    = (const float*)d_in[4];
    const float* table2    = (const float*)d_in[5];
    const float* table3    = (const float*)d_in[6];
    const float* st1       = (const float*)d_in[7];
    const float* st2       = (const float*)d_in[8];
    const float* tf3       = (const float*)d_in[9];
    const float* rms_scale = (const float*)d_in[10];
    const float* w_down    = (const float*)d_in[11];
    const float* w_final   = (const float*)d_in[12];
    const float* b_final   = (const float*)d_in[13];
    float* out = (float*)d_out;

    wf_precompute_kernel<<<(NK8 * 4 * 32 + 255) / 256, 256>>>(w_down, rms_scale);
    stlt_fused_kernel<<<8192 / MPTS, TPB>>>(
        pos, dirv, t, table0, table1, table2, table3, st1, st2, tf3,
        w_final, b_final, out);
}